// round 15
// baseline (speedup 1.0000x reference)
#include <cuda_runtime.h>
#include <cuda_fp16.h>
#include <cstdint>

// Problem constants
#define B_  8
#define N_  6144
#define D_  16
#define K_  3
#define O_  64
#define BD_ 128             // B*D columns
#define TK2_ 128            // k-tile (two 64-wide subtiles)
#define NSTEP2_ (N_ / TK2_) // 48

// ------------- global scratch (no cudaMalloc allowed) ----------------------
__device__ __half g_Xf[(size_t)BD_ * N_];          // X^T fp16 [col j][k]
__device__ float  g_Y [(size_t)K_ * N_ * BD_];

// ------------- PTX helpers --------------------------------------------------
__device__ __forceinline__ unsigned smem_u32(const void* p) {
    return (unsigned)__cvta_generic_to_shared(p);
}
__device__ __forceinline__ void cp_async16(unsigned dst, const void* gsrc) {
    asm volatile("cp.async.cg.shared.global [%0], [%1], 16;\n" :: "r"(dst), "l"(gsrc));
}
__device__ __forceinline__ void cp_commit() {
    asm volatile("cp.async.commit_group;\n" ::: "memory");
}
template<int NW> __device__ __forceinline__ void cp_wait() {
    asm volatile("cp.async.wait_group %0;\n" :: "n"(NW) : "memory");
}
__device__ __forceinline__ void sts64(unsigned addr, unsigned long long v) {
    asm volatile("st.shared.b64 [%0], %1;" :: "r"(addr), "l"(v) : "memory");
}
__device__ __forceinline__ void ldsm_x4(unsigned& r0, unsigned& r1,
                                        unsigned& r2, unsigned& r3, unsigned addr) {
    asm volatile("ldmatrix.sync.aligned.m8n8.x4.shared.b16 {%0,%1,%2,%3}, [%4];"
                 : "=r"(r0), "=r"(r1), "=r"(r2), "=r"(r3) : "r"(addr));
}
// D(f32) += A(f16) * B(f16), m16n8k16, row.col
__device__ __forceinline__ void mma16816(float* d, const unsigned* a,
                                         const unsigned* b) {
    asm volatile(
        "mma.sync.aligned.m16n8k16.row.col.f32.f16.f16.f32 "
        "{%0,%1,%2,%3}, {%4,%5,%6,%7}, {%8,%9}, {%0,%1,%2,%3};"
        : "+f"(d[0]), "+f"(d[1]), "+f"(d[2]), "+f"(d[3])
        : "r"(a[0]), "r"(a[1]), "r"(a[2]), "r"(a[3]), "r"(b[0]), "r"(b[1]));
}

#define SMEM_SWIZZLE_128B(o) ((o) ^ (((o) >> 3) & 0x70))

// pack two floats -> fp16x2 (lo = x, hi = y)
__device__ __forceinline__ unsigned cvt_f16x2(float x, float y) {
    unsigned r;
    asm("cvt.rn.f16x2.f32 %0, %1, %2;" : "=r"(r) : "f"(y), "f"(x));
    return r;
}
// packed dual-fp32 helpers (out_kernel)
__device__ __forceinline__ unsigned long long pack2(float x, float y) {
    unsigned long long r;
    asm("mov.b64 %0, {%1, %2};" : "=l"(r) : "f"(x), "f"(y));
    return r;
}
__device__ __forceinline__ void unpack2(unsigned long long v, float& x, float& y) {
    asm("mov.b64 {%0, %1}, %2;" : "=f"(x), "=f"(y) : "l"(v));
}
__device__ __forceinline__ void fma2(unsigned long long& c,
                                     unsigned long long a,
                                     unsigned long long b) {
    asm("fma.rn.f32x2 %0, %1, %2, %0;" : "+l"(c) : "l"(a), "l"(b));
}
__device__ __forceinline__ void lds_2xu64(unsigned long long& a,
                                          unsigned long long& b, unsigned addr) {
    asm("ld.shared.v2.u64 {%0, %1}, [%2];" : "=l"(a), "=l"(b) : "r"(addr));
}

// ------------- smem layout per block: 2 buf x (A:32KB + B:32KB) = 128KB -----
#define OFF_A(buf,h)  ((buf) * 65536 + (h) * 16384)
#define OFF_Bt(buf,h) ((buf) * 65536 + 32768 + (h) * 16384)
#define SMEM_BYTES 131072

// ------------- Kernel 0: X^T -> fp16 (smem transpose, 384 blocks) -----------
__global__ __launch_bounds__(256)
void xsplit_kernel(const float* __restrict__ inputs) {
    __shared__ float S[16][129];

    const int t  = threadIdx.x;
    const int m0 = blockIdx.x * 16;

    #pragma unroll
    for (int r = 0; r < 8; ++r) {
        const int idx = t + r * 256;
        const int ml  = idx >> 7;
        const int c   = idx & 127;
        const int b   = c >> 4, d = c & 15;
        S[ml][c] = inputs[((size_t)b * N_ + m0 + ml) * D_ + d];
    }
    __syncthreads();

    const int c  = t & 127;
    const int ms = (t >> 7) * 8;
    uint4 v;
    v.x = cvt_f16x2(S[ms + 0][c], S[ms + 1][c]);
    v.y = cvt_f16x2(S[ms + 2][c], S[ms + 3][c]);
    v.z = cvt_f16x2(S[ms + 4][c], S[ms + 5][c]);
    v.w = cvt_f16x2(S[ms + 6][c], S[ms + 7][c]);
    *reinterpret_cast<uint4*>(&g_Xf[(size_t)c * N_ + m0 + ms]) = v;
}

// ------------- Kernel 1: fp16 GEMM, C=128x128, 16 warps, 32x64 warp tiles ---
// grid = (48, 3) = 144 blocks (1 wave, 1 CTA/SM). 256 threads.
// A-convert STS interleaved into the ks loop (2 per step) to keep the tensor
// pipe fed across the tile boundary.
__global__ __launch_bounds__(256, 1)
void gemm_mma_kernel(const float* __restrict__ supports) {
    extern __shared__ char smem_raw[];
    const unsigned sbase = smem_u32(smem_raw);

    const int t    = threadIdx.x;
    const int wid  = t >> 5;
    const int lane = t & 31;
    const int row0 = blockIdx.x * 128;

    const float* A = supports + (size_t)blockIdx.y * N_ * N_;
    float*       C = g_Y      + (size_t)blockIdx.y * N_ * BD_;

    const int wm0 = (wid >> 1) * 32;    // 0,32,64,96
    const int wn0 = (wid & 1) * 64;     // 0,64

    // loader mapping (A): 16 threads per row, float4 each
    const int a_sub = t >> 4;           // 0..15
    const int a_c4  = (t & 15) << 2;    // float col 0..60 within 64-k subtile

    // ldmatrix lane address components
    const int a_r  = lane & 15;
    const int a_k8 = (lane >> 4) << 3;
    const int b_n  = ((lane >> 4) << 3) + (lane & 7);
    const int b_k8 = ((lane >> 3) & 1) << 3;

    float acc[2][8][4];
    #pragma unroll
    for (int i = 0; i < 2; ++i)
        #pragma unroll
        for (int j = 0; j < 8; ++j)
            #pragma unroll
            for (int p = 0; p < 4; ++p) acc[i][j][p] = 0.f;

    // av[p]: h = p>>3 (subtile), row = (p&7)*16 + a_sub
    float4 av[16];

    // ---- prologue
    #pragma unroll
    for (int p = 0; p < 16; ++p) {
        const int h   = p >> 3;
        const int row = (p & 7) * 16 + a_sub;
        av[p] = __ldg(reinterpret_cast<const float4*>(
            &A[(size_t)(row0 + row) * N_ + h * 64 + a_c4]));
    }
    #pragma unroll
    for (int h = 0; h < 2; ++h)
        #pragma unroll
        for (int j = 0; j < 4; ++j) {
            const int c   = t + j * 256;       // 16B chunk (0..1023)
            const int r   = c >> 3;            // B row (n col) 0..127
            const int kin = (c & 7) << 3;
            const unsigned swz = SMEM_SWIZZLE_128B((unsigned)(c << 4));
            cp_async16(sbase + OFF_Bt(0, h) + swz,
                       &g_Xf[(size_t)r * N_ + h * 64 + kin]);
        }
    cp_commit();
    #pragma unroll
    for (int p = 0; p < 16; ++p) {
        const int h   = p >> 3;
        const int row = (p & 7) * 16 + a_sub;
        const unsigned boff = (unsigned)(row * 128 + (a_c4 << 1));
        const unsigned swz  = SMEM_SWIZZLE_128B(boff);
        unsigned h01 = cvt_f16x2(av[p].x, av[p].y);
        unsigned h23 = cvt_f16x2(av[p].z, av[p].w);
        sts64(sbase + OFF_A(0, h) + swz, ((unsigned long long)h23 << 32) | h01);
    }

    for (int kt = 0; kt < NSTEP2_; ++kt) {
        const int buf  = kt & 1;
        const int nbuf = buf ^ 1;
        const bool more = (kt + 1 < NSTEP2_);

        // A LDGs for kt+1 before the wait/barrier (register-only; old av
        // already consumed by the interleaved STS during iteration kt-1)
        if (more) {
            const int kk2 = (kt + 1) * TK2_;
            #pragma unroll
            for (int p = 0; p < 16; ++p) {
                const int h   = p >> 3;
                const int row = (p & 7) * 16 + a_sub;
                av[p] = __ldg(reinterpret_cast<const float4*>(
                    &A[(size_t)(row0 + row) * N_ + kk2 + h * 64 + a_c4]));
            }
        }

        cp_wait<0>();
        __syncthreads();   // buf tiles visible; prior compute done

        // B cp.async for kt+1 into nbuf
        if (more) {
            const int kk2 = (kt + 1) * TK2_;
            #pragma unroll
            for (int h = 0; h < 2; ++h)
                #pragma unroll
                for (int j = 0; j < 4; ++j) {
                    const int c   = t + j * 256;
                    const int r   = c >> 3;
                    const int kin = (c & 7) << 3;
                    const unsigned swz = SMEM_SWIZZLE_128B((unsigned)(c << 4));
                    cp_async16(sbase + OFF_Bt(nbuf, h) + swz,
                               &g_Xf[(size_t)r * N_ + kk2 + h * 64 + kin]);
                }
            cp_commit();
        }

        // ---- compute on buf: 8 k16 steps (2 subtiles x 4), 16 MMAs each.
        //      2 of the 16 A-convert STS (into nbuf) interleaved per step.
        #pragma unroll
        for (int ks = 0; ks < 8; ++ks) {
            const int h    = ks >> 2;
            const int kk16 = (ks & 3) * 16;
            const unsigned a_base = sbase + OFF_A(buf, h);
            const unsigned b_base = sbase + OFF_Bt(buf, h);

            unsigned af[2][4];
            #pragma unroll
            for (int mt = 0; mt < 2; ++mt) {
                const unsigned off = SMEM_SWIZZLE_128B(
                    (unsigned)((wm0 + mt * 16 + a_r) * 128 + (kk16 + a_k8) * 2));
                ldsm_x4(af[mt][0], af[mt][1], af[mt][2], af[mt][3], a_base + off);
            }
            unsigned bf[8][2];
            #pragma unroll
            for (int np = 0; np < 4; ++np) {
                const unsigned off = SMEM_SWIZZLE_128B(
                    (unsigned)((wn0 + np * 16 + b_n) * 128 + (kk16 + b_k8) * 2));
                ldsm_x4(bf[np*2][0], bf[np*2][1], bf[np*2+1][0], bf[np*2+1][1],
                        b_base + off);
            }
            #pragma unroll
            for (int mt = 0; mt < 2; ++mt)
                #pragma unroll
                for (int nt = 0; nt < 8; ++nt)
                    mma16816(acc[mt][nt], af[mt], bf[nt]);

            // interleaved A-convert: 2 STS per ks step (p = 2*ks, 2*ks+1)
            if (more) {
                #pragma unroll
                for (int e = 0; e < 2; ++e) {
                    const int p   = ks * 2 + e;
                    const int hh  = p >> 3;
                    const int row = (p & 7) * 16 + a_sub;
                    const unsigned boff = (unsigned)(row * 128 + (a_c4 << 1));
                    const unsigned swz  = SMEM_SWIZZLE_128B(boff);
                    unsigned h01 = cvt_f16x2(av[p].x, av[p].y);
                    unsigned h23 = cvt_f16x2(av[p].z, av[p].w);
                    sts64(sbase + OFF_A(nbuf, hh) + swz,
                          ((unsigned long long)h23 << 32) | h01);
                }
            }
        }
    }

    // ---- epilogue: write accumulators to g_Y (fp32)
    const int lr = lane >> 2;
    const int lc = (lane & 3) << 1;
    #pragma unroll
    for (int mt = 0; mt < 2; ++mt) {
        #pragma unroll
        for (int nt = 0; nt < 8; ++nt) {
            const int m = row0 + wm0 + mt * 16 + lr;
            const int n = wn0 + nt * 8 + lc;
            float2 v0 = make_float2(acc[mt][nt][0], acc[mt][nt][1]);
            float2 v1 = make_float2(acc[mt][nt][2], acc[mt][nt][3]);
            *reinterpret_cast<float2*>(&C[(size_t)m * BD_ + n])       = v0;
            *reinterpret_cast<float2*>(&C[(size_t)(m + 8) * BD_ + n]) = v1;
        }
    }
}

// ------------- Kernel 2: out = (Y + I-term) @ W^T + b  (f32x2 packed) -------
__global__ __launch_bounds__(256)
void out_kernel(const float* __restrict__ inputs,
                const float* __restrict__ W,
                const float* __restrict__ bias,
                float* __restrict__ out) {
    __shared__ float Ysh[3][16][128];

    const int n0 = blockIdx.x * 16;
    const int t  = threadIdx.x;
    const int o  = t & 63;
    const int g  = t >> 6;

    for (int idx = t; idx < 3 * 16 * 128; idx += 256) {
        const int kk = idx / (16 * 128);
        const int nn = (idx >> 7) & 15;
        const int c  = idx & 127;
        const int b  = c >> 4;
        const int d  = c & 15;
        const int n  = n0 + nn;
        Ysh[kk][nn][c] = g_Y[(size_t)kk * N_ * BD_ + (size_t)n * BD_ + c]
                       + inputs[((size_t)b * N_ + n) * D_ + d];
    }

    unsigned long long wp[3][8];
    #pragma unroll
    for (int kk = 0; kk < 3; ++kk)
        #pragma unroll
        for (int q = 0; q < 8; ++q)
            wp[kk][q] = pack2(W[o * 48 + (2 * q) * 3 + kk],
                              W[o * 48 + (2 * q + 1) * 3 + kk]);
    const float bo = bias[o];

    __syncthreads();

    const unsigned ysh_base = smem_u32(&Ysh[0][0][0]);

    #pragma unroll 4
    for (int pp = 0; pp < 32; ++pp) {
        const int pair = g * 32 + pp;
        const int nn = pair >> 3;
        const int b  = pair & 7;
        unsigned long long acc0 = pack2(bo, 0.f);
        unsigned long long acc1 = 0ull;
        #pragma unroll
        for (int kk = 0; kk < 3; ++kk) {
            const unsigned zaddr = ysh_base
                + (unsigned)((kk * 16 * 128 + nn * 128 + b * 16) * 4);
            #pragma unroll
            for (int q4 = 0; q4 < 4; ++q4) {
                unsigned long long z01, z23;
                lds_2xu64(z01, z23, zaddr + q4 * 16);
                fma2(acc0, z01, wp[kk][q4 * 2]);
                fma2(acc1, z23, wp[kk][q4 * 2 + 1]);
            }
        }
        float l0, h0, l1, h1;
        unpack2(acc0, l0, h0);
        unpack2(acc1, l1, h1);
        out[((size_t)b * N_ + n0 + nn) * O_ + o] = (l0 + h0) + (l1 + h1);
    }
}

// ------------- launch -------------------------------------------------------
extern "C" void kernel_launch(void* const* d_in, const int* in_sizes, int n_in,
                              void* d_out, int out_size) {
    const float* inputs = nullptr;
    const float* supports = nullptr;
    const float* W = nullptr;
    const float* bias = nullptr;
    for (int i = 0; i < n_in; ++i) {
        if      (in_sizes[i] == B_ * N_ * D_) inputs   = (const float*)d_in[i];
        else if (in_sizes[i] == K_ * N_ * N_) supports = (const float*)d_in[i];
        else if (in_sizes[i] == O_ * D_ * K_) W        = (const float*)d_in[i];
        else if (in_sizes[i] == O_)           bias     = (const float*)d_in[i];
    }
    float* out = (float*)d_out;

    cudaFuncSetAttribute(gemm_mma_kernel,
                         cudaFuncAttributeMaxDynamicSharedMemorySize, SMEM_BYTES);

    xsplit_kernel<<<N_ / 16, 256>>>(inputs);
    gemm_mma_kernel<<<dim3(N_ / 128, K_), 256, SMEM_BYTES>>>(supports);
    out_kernel<<<N_ / 16, 256>>>(inputs, W, bias, out);
}

// round 16
// speedup vs baseline: 1.0687x; 1.0687x over previous
#include <cuda_runtime.h>
#include <cuda_fp16.h>
#include <cstdint>

// Problem constants
#define B_  8
#define N_  6144
#define D_  16
#define K_  3
#define O_  64
#define BD_ 128             // B*D columns
#define TK2_ 128            // k-tile (two 64-wide subtiles)
#define NSTEP2_ (N_ / TK2_) // 48

// ------------- global scratch (no cudaMalloc allowed) ----------------------
__device__ __half g_Xf[(size_t)BD_ * N_];          // X^T fp16 [col j][k]
__device__ float  g_Y [(size_t)K_ * N_ * BD_];

// ------------- PTX helpers --------------------------------------------------
__device__ __forceinline__ unsigned smem_u32(const void* p) {
    return (unsigned)__cvta_generic_to_shared(p);
}
__device__ __forceinline__ void cp_async16(unsigned dst, const void* gsrc) {
    asm volatile("cp.async.cg.shared.global [%0], [%1], 16;\n" :: "r"(dst), "l"(gsrc));
}
__device__ __forceinline__ void cp_commit() {
    asm volatile("cp.async.commit_group;\n" ::: "memory");
}
template<int NW> __device__ __forceinline__ void cp_wait() {
    asm volatile("cp.async.wait_group %0;\n" :: "n"(NW) : "memory");
}
__device__ __forceinline__ void sts64(unsigned addr, unsigned long long v) {
    asm volatile("st.shared.b64 [%0], %1;" :: "r"(addr), "l"(v) : "memory");
}
__device__ __forceinline__ void ldsm_x4(unsigned& r0, unsigned& r1,
                                        unsigned& r2, unsigned& r3, unsigned addr) {
    asm volatile("ldmatrix.sync.aligned.m8n8.x4.shared.b16 {%0,%1,%2,%3}, [%4];"
                 : "=r"(r0), "=r"(r1), "=r"(r2), "=r"(r3) : "r"(addr));
}
// D(f32) += A(f16) * B(f16), m16n8k16, row.col
__device__ __forceinline__ void mma16816(float* d, const unsigned* a,
                                         const unsigned* b) {
    asm volatile(
        "mma.sync.aligned.m16n8k16.row.col.f32.f16.f16.f32 "
        "{%0,%1,%2,%3}, {%4,%5,%6,%7}, {%8,%9}, {%0,%1,%2,%3};"
        : "+f"(d[0]), "+f"(d[1]), "+f"(d[2]), "+f"(d[3])
        : "r"(a[0]), "r"(a[1]), "r"(a[2]), "r"(a[3]), "r"(b[0]), "r"(b[1]));
}

#define SMEM_SWIZZLE_128B(o) ((o) ^ (((o) >> 3) & 0x70))

// pack two floats -> fp16x2 (lo = x, hi = y)
__device__ __forceinline__ unsigned cvt_f16x2(float x, float y) {
    unsigned r;
    asm("cvt.rn.f16x2.f32 %0, %1, %2;" : "=r"(r) : "f"(y), "f"(x));
    return r;
}
// packed dual-fp32 helpers (out_kernel)
__device__ __forceinline__ unsigned long long pack2(float x, float y) {
    unsigned long long r;
    asm("mov.b64 %0, {%1, %2};" : "=l"(r) : "f"(x), "f"(y));
    return r;
}
__device__ __forceinline__ void unpack2(unsigned long long v, float& x, float& y) {
    asm("mov.b64 {%0, %1}, %2;" : "=f"(x), "=f"(y) : "l"(v));
}
__device__ __forceinline__ void fma2(unsigned long long& c,
                                     unsigned long long a,
                                     unsigned long long b) {
    asm("fma.rn.f32x2 %0, %1, %2, %0;" : "+l"(c) : "l"(a), "l"(b));
}
__device__ __forceinline__ void lds_2xu64(unsigned long long& a,
                                          unsigned long long& b, unsigned addr) {
    asm("ld.shared.v2.u64 {%0, %1}, [%2];" : "=l"(a), "=l"(b) : "r"(addr));
}

// ------------- smem layout per block: 2 buf x (A:32KB + B:32KB) = 128KB -----
#define OFF_A(buf,h)  ((buf) * 65536 + (h) * 16384)
#define OFF_Bt(buf,h) ((buf) * 65536 + 32768 + (h) * 16384)
#define SMEM_BYTES 131072

// ------------- Kernel 0: X^T -> fp16 (smem transpose, 768 blocks) -----------
// Block: 8 m-rows x 128 (b*16+d) cols. grid = N/8 = 768. 256 threads.
__global__ __launch_bounds__(256)
void xsplit_kernel(const float* __restrict__ inputs) {
    __shared__ float S[8][129];     // +1 pad: conflict-free column reads

    const int t  = threadIdx.x;
    const int m0 = blockIdx.x * 8;

    // coalesced load: consecutive t -> consecutive (b,d) within a row
    #pragma unroll
    for (int r = 0; r < 4; ++r) {
        const int idx = t + r * 256;       // 0..1023
        const int ml  = idx >> 7;          // m_local 0..7
        const int c   = idx & 127;         // b*16+d
        const int b   = c >> 4, d = c & 15;
        S[ml][c] = inputs[((size_t)b * N_ + m0 + ml) * D_ + d];
    }
    __syncthreads();

    // one uint2 (4 packed halves) per thread; thread pairs form 16B segments
    const int c  = t >> 1;                 // 0..127
    const int ms = (t & 1) * 4;            // 0 or 4
    uint2 v;
    v.x = cvt_f16x2(S[ms + 0][c], S[ms + 1][c]);
    v.y = cvt_f16x2(S[ms + 2][c], S[ms + 3][c]);
    *reinterpret_cast<uint2*>(&g_Xf[(size_t)c * N_ + m0 + ms]) = v;
}

// ------------- Kernel 1: fp16 GEMM, C=128x128, 16 warps, 32x64 warp tiles ---
// (R14 config verbatim — best measured.) grid = (48, 3) = 144 blocks.
__global__ __launch_bounds__(256, 1)
void gemm_mma_kernel(const float* __restrict__ supports) {
    extern __shared__ char smem_raw[];
    const unsigned sbase = smem_u32(smem_raw);

    const int t    = threadIdx.x;
    const int wid  = t >> 5;
    const int lane = t & 31;
    const int row0 = blockIdx.x * 128;

    const float* A = supports + (size_t)blockIdx.y * N_ * N_;
    float*       C = g_Y      + (size_t)blockIdx.y * N_ * BD_;

    const int wm0 = (wid >> 1) * 32;    // 0,32,64,96
    const int wn0 = (wid & 1) * 64;     // 0,64

    const int a_sub = t >> 4;           // 0..15
    const int a_c4  = (t & 15) << 2;    // float col 0..60 within 64-k subtile

    const int a_r  = lane & 15;
    const int a_k8 = (lane >> 4) << 3;
    const int b_n  = ((lane >> 4) << 3) + (lane & 7);
    const int b_k8 = ((lane >> 3) & 1) << 3;

    float acc[2][8][4];
    #pragma unroll
    for (int i = 0; i < 2; ++i)
        #pragma unroll
        for (int j = 0; j < 8; ++j)
            #pragma unroll
            for (int p = 0; p < 4; ++p) acc[i][j][p] = 0.f;

    // av[p]: h = p>>3 (subtile), row = (p&7)*16 + a_sub
    float4 av[16];

    // ---- prologue
    #pragma unroll
    for (int p = 0; p < 16; ++p) {
        const int h   = p >> 3;
        const int row = (p & 7) * 16 + a_sub;
        av[p] = __ldg(reinterpret_cast<const float4*>(
            &A[(size_t)(row0 + row) * N_ + h * 64 + a_c4]));
    }
    #pragma unroll
    for (int h = 0; h < 2; ++h)
        #pragma unroll
        for (int j = 0; j < 4; ++j) {
            const int c   = t + j * 256;       // 16B chunk (0..1023)
            const int r   = c >> 3;            // B row (n col) 0..127
            const int kin = (c & 7) << 3;
            const unsigned swz = SMEM_SWIZZLE_128B((unsigned)(c << 4));
            cp_async16(sbase + OFF_Bt(0, h) + swz,
                       &g_Xf[(size_t)r * N_ + h * 64 + kin]);
        }
    cp_commit();
    #pragma unroll
    for (int p = 0; p < 16; ++p) {
        const int h   = p >> 3;
        const int row = (p & 7) * 16 + a_sub;
        const unsigned boff = (unsigned)(row * 128 + (a_c4 << 1));
        const unsigned swz  = SMEM_SWIZZLE_128B(boff);
        unsigned h01 = cvt_f16x2(av[p].x, av[p].y);
        unsigned h23 = cvt_f16x2(av[p].z, av[p].w);
        sts64(sbase + OFF_A(0, h) + swz, ((unsigned long long)h23 << 32) | h01);
    }

    for (int kt = 0; kt < NSTEP2_; ++kt) {
        const int buf  = kt & 1;
        const int nbuf = buf ^ 1;

        // A LDGs for kt+1 before the wait/barrier (register-only)
        if (kt + 1 < NSTEP2_) {
            const int kk2 = (kt + 1) * TK2_;
            #pragma unroll
            for (int p = 0; p < 16; ++p) {
                const int h   = p >> 3;
                const int row = (p & 7) * 16 + a_sub;
                av[p] = __ldg(reinterpret_cast<const float4*>(
                    &A[(size_t)(row0 + row) * N_ + kk2 + h * 64 + a_c4]));
            }
        }

        cp_wait<0>();
        __syncthreads();   // buf tiles visible; prior compute done

        // B cp.async for kt+1 into nbuf
        if (kt + 1 < NSTEP2_) {
            const int kk2 = (kt + 1) * TK2_;
            #pragma unroll
            for (int h = 0; h < 2; ++h)
                #pragma unroll
                for (int j = 0; j < 4; ++j) {
                    const int c   = t + j * 256;
                    const int r   = c >> 3;
                    const int kin = (c & 7) << 3;
                    const unsigned swz = SMEM_SWIZZLE_128B((unsigned)(c << 4));
                    cp_async16(sbase + OFF_Bt(nbuf, h) + swz,
                               &g_Xf[(size_t)r * N_ + kk2 + h * 64 + kin]);
                }
            cp_commit();
        }

        // ---- compute on buf: 8 k16 steps (2 subtiles x 4), 16 MMAs each
        #pragma unroll
        for (int ks = 0; ks < 8; ++ks) {
            const int h    = ks >> 2;
            const int kk16 = (ks & 3) * 16;
            const unsigned a_base = sbase + OFF_A(buf, h);
            const unsigned b_base = sbase + OFF_Bt(buf, h);

            unsigned af[2][4];
            #pragma unroll
            for (int mt = 0; mt < 2; ++mt) {
                const unsigned off = SMEM_SWIZZLE_128B(
                    (unsigned)((wm0 + mt * 16 + a_r) * 128 + (kk16 + a_k8) * 2));
                ldsm_x4(af[mt][0], af[mt][1], af[mt][2], af[mt][3], a_base + off);
            }
            unsigned bf[8][2];
            #pragma unroll
            for (int np = 0; np < 4; ++np) {
                const unsigned off = SMEM_SWIZZLE_128B(
                    (unsigned)((wn0 + np * 16 + b_n) * 128 + (kk16 + b_k8) * 2));
                ldsm_x4(bf[np*2][0], bf[np*2][1], bf[np*2+1][0], bf[np*2+1][1],
                        b_base + off);
            }
            #pragma unroll
            for (int mt = 0; mt < 2; ++mt)
                #pragma unroll
                for (int nt = 0; nt < 8; ++nt)
                    mma16816(acc[mt][nt], af[mt], bf[nt]);
        }

        // convert prefetched A regs -> fp16 into nbuf (phase-separated block;
        // R15 showed interleaving this into the ks loop regresses)
        if (kt + 1 < NSTEP2_) {
            #pragma unroll
            for (int p = 0; p < 16; ++p) {
                const int h   = p >> 3;
                const int row = (p & 7) * 16 + a_sub;
                const unsigned boff = (unsigned)(row * 128 + (a_c4 << 1));
                const unsigned swz  = SMEM_SWIZZLE_128B(boff);
                unsigned h01 = cvt_f16x2(av[p].x, av[p].y);
                unsigned h23 = cvt_f16x2(av[p].z, av[p].w);
                sts64(sbase + OFF_A(nbuf, h) + swz,
                      ((unsigned long long)h23 << 32) | h01);
            }
        }
    }

    // ---- epilogue: write accumulators to g_Y (fp32)
    const int lr = lane >> 2;
    const int lc = (lane & 3) << 1;
    #pragma unroll
    for (int mt = 0; mt < 2; ++mt) {
        #pragma unroll
        for (int nt = 0; nt < 8; ++nt) {
            const int m = row0 + wm0 + mt * 16 + lr;
            const int n = wn0 + nt * 8 + lc;
            float2 v0 = make_float2(acc[mt][nt][0], acc[mt][nt][1]);
            float2 v1 = make_float2(acc[mt][nt][2], acc[mt][nt][3]);
            *reinterpret_cast<float2*>(&C[(size_t)m * BD_ + n])       = v0;
            *reinterpret_cast<float2*>(&C[(size_t)(m + 8) * BD_ + n]) = v1;
        }
    }
}

// ------------- Kernel 2: out = (Y + I-term) @ W^T + b  (f32x2 packed) -------
__global__ __launch_bounds__(256)
void out_kernel(const float* __restrict__ inputs,
                const float* __restrict__ W,
                const float* __restrict__ bias,
                float* __restrict__ out) {
    __shared__ float Ysh[3][16][128];

    const int n0 = blockIdx.x * 16;
    const int t  = threadIdx.x;
    const int o  = t & 63;
    const int g  = t >> 6;

    for (int idx = t; idx < 3 * 16 * 128; idx += 256) {
        const int kk = idx / (16 * 128);
        const int nn = (idx >> 7) & 15;
        const int c  = idx & 127;
        const int b  = c >> 4;
        const int d  = c & 15;
        const int n  = n0 + nn;
        Ysh[kk][nn][c] = g_Y[(size_t)kk * N_ * BD_ + (size_t)n * BD_ + c]
                       + inputs[((size_t)b * N_ + n) * D_ + d];
    }

    unsigned long long wp[3][8];
    #pragma unroll
    for (int kk = 0; kk < 3; ++kk)
        #pragma unroll
        for (int q = 0; q < 8; ++q)
            wp[kk][q] = pack2(W[o * 48 + (2 * q) * 3 + kk],
                              W[o * 48 + (2 * q + 1) * 3 + kk]);
    const float bo = bias[o];

    __syncthreads();

    const unsigned ysh_base = smem_u32(&Ysh[0][0][0]);

    #pragma unroll 4
    for (int pp = 0; pp < 32; ++pp) {
        const int pair = g * 32 + pp;
        const int nn = pair >> 3;
        const int b  = pair & 7;
        unsigned long long acc0 = pack2(bo, 0.f);
        unsigned long long acc1 = 0ull;
        #pragma unroll
        for (int kk = 0; kk < 3; ++kk) {
            const unsigned zaddr = ysh_base
                + (unsigned)((kk * 16 * 128 + nn * 128 + b * 16) * 4);
            #pragma unroll
            for (int q4 = 0; q4 < 4; ++q4) {
                unsigned long long z01, z23;
                lds_2xu64(z01, z23, zaddr + q4 * 16);
                fma2(acc0, z01, wp[kk][q4 * 2]);
                fma2(acc1, z23, wp[kk][q4 * 2 + 1]);
            }
        }
        float l0, h0, l1, h1;
        unpack2(acc0, l0, h0);
        unpack2(acc1, l1, h1);
        out[((size_t)b * N_ + n0 + nn) * O_ + o] = (l0 + h0) + (l1 + h1);
    }
}

// ------------- launch -------------------------------------------------------
extern "C" void kernel_launch(void* const* d_in, const int* in_sizes, int n_in,
                              void* d_out, int out_size) {
    const float* inputs = nullptr;
    const float* supports = nullptr;
    const float* W = nullptr;
    const float* bias = nullptr;
    for (int i = 0; i < n_in; ++i) {
        if      (in_sizes[i] == B_ * N_ * D_) inputs   = (const float*)d_in[i];
        else if (in_sizes[i] == K_ * N_ * N_) supports = (const float*)d_in[i];
        else if (in_sizes[i] == O_ * D_ * K_) W        = (const float*)d_in[i];
        else if (in_sizes[i] == O_)           bias     = (const float*)d_in[i];
    }
    float* out = (float*)d_out;

    cudaFuncSetAttribute(gemm_mma_kernel,
                         cudaFuncAttributeMaxDynamicSharedMemorySize, SMEM_BYTES);

    xsplit_kernel<<<N_ / 8, 256>>>(inputs);
    gemm_mma_kernel<<<dim3(N_ / 128, K_), 256, SMEM_BYTES>>>(supports);
    out_kernel<<<N_ / 16, 256>>>(inputs, W, bias, out);
}